// round 1
// baseline (speedup 1.0000x reference)
#include <cuda_runtime.h>
#include <math.h>

// Depthwise 5x5 Gaussian blur, separable two-pass in shared memory.
// x: [16, 256, 64, 64] f32, sigma: [1] f32. One block per 64x64 plane.

#define HH 64
#define WW 64
#define IN_STRIDE 72   // 4 halo cols + 64 data + 4 halo cols (keeps float4 windows aligned)
#define TPB 256

__global__ __launch_bounds__(TPB) void gauss5_kernel(const float* __restrict__ x,
                                                     const float* __restrict__ sigma_p,
                                                     float* __restrict__ out)
{
    __shared__ float sin_[HH * IN_STRIDE];     // input plane, data at cols 4..67, zero halos
    __shared__ float stmp[(HH + 4) * WW];      // horizontal result, data rows 2..65, zero halo rows

    const int tid = threadIdx.x;
    const long plane = blockIdx.x;             // n*C + c
    const float* gin = x + plane * (long)(HH * WW);
    float* gout = out + plane * (long)(HH * WW);

    // --- Gaussian taps (symmetric): g(d) = exp(-d^2 / (2 sigma^2)), d in {-2..2}
    const float sigma = sigma_p[0];
    const float inv2s2 = 1.0f / (2.0f * sigma * sigma);
    const float g0 = expf(-4.0f * inv2s2);   // |d| = 2
    const float g1 = expf(-1.0f * inv2s2);   // |d| = 1
    const float g2 = 1.0f;                   // d = 0
    const float s1 = 2.0f * (g0 + g1) + g2;
    const float invn = 1.0f / (s1 * s1);     // 2D normalization

    // --- zero input column halos: 64 rows x 8 cols = 512 floats (2 per thread)
    {
        int i = tid;
        #pragma unroll
        for (int k = 0; k < 2; k++, i += TPB) {
            int r = i >> 3;
            int c = i & 7;
            int col = (c < 4) ? c : (c - 4 + 68);
            sin_[r * IN_STRIDE + col] = 0.0f;
        }
    }
    // --- zero temp row halos: rows {0,1,66,67} x 64 = 256 floats (1 per thread)
    {
        int r = tid >> 6;          // 0..3
        int c = tid & 63;
        int row = (r < 2) ? r : (r - 2 + 66);
        stmp[row * WW + c] = 0.0f;
    }

    // --- load plane: 1024 float4, fully coalesced
    #pragma unroll
    for (int i = 0; i < 4; i++) {
        int idx = tid + i * TPB;          // 0..1023
        int r = idx >> 4;
        int qc = idx & 15;
        float4 v = reinterpret_cast<const float4*>(gin)[idx];
        *reinterpret_cast<float4*>(&sin_[r * IN_STRIDE + 4 + qc * 4]) = v;
    }
    __syncthreads();

    // --- horizontal pass: temp[r][c] = sum_d g[d] * in[r][c+d]
    #pragma unroll
    for (int i = 0; i < 4; i++) {
        int idx = tid + i * TPB;
        int r = idx >> 4;
        int c4 = (idx & 15) << 2;                       // output col base
        const float* row = &sin_[r * IN_STRIDE + 4 + c4];
        float4 a = *reinterpret_cast<const float4*>(row - 4);  // cols c4-4..c4-1
        float4 b = *reinterpret_cast<const float4*>(row);      // cols c4  ..c4+3
        float4 d = *reinterpret_cast<const float4*>(row + 4);  // cols c4+4..c4+7
        float w0 = a.z, w1 = a.w, w2 = b.x, w3 = b.y;
        float w4 = b.z, w5 = b.w, w6 = d.x, w7 = d.y;          // cols c4-2 .. c4+5
        float4 t;
        t.x = g0 * (w0 + w4) + g1 * (w1 + w3) + g2 * w2;
        t.y = g0 * (w1 + w5) + g1 * (w2 + w4) + g2 * w3;
        t.z = g0 * (w2 + w6) + g1 * (w3 + w5) + g2 * w4;
        t.w = g0 * (w3 + w7) + g1 * (w4 + w6) + g2 * w5;
        *reinterpret_cast<float4*>(&stmp[(r + 2) * WW + c4]) = t;
    }
    __syncthreads();

    // --- vertical pass + normalize + store
    #pragma unroll
    for (int i = 0; i < 4; i++) {
        int idx = tid + i * TPB;
        int r = idx >> 4;
        int c4 = (idx & 15) << 2;
        const float* col = &stmp[r * WW + c4];   // padded rows r..r+4 == real rows r-2..r+2
        float4 t0 = *reinterpret_cast<const float4*>(col);
        float4 t1 = *reinterpret_cast<const float4*>(col + WW);
        float4 t2 = *reinterpret_cast<const float4*>(col + 2 * WW);
        float4 t3 = *reinterpret_cast<const float4*>(col + 3 * WW);
        float4 t4 = *reinterpret_cast<const float4*>(col + 4 * WW);
        float4 o;
        o.x = (g0 * (t0.x + t4.x) + g1 * (t1.x + t3.x) + g2 * t2.x) * invn;
        o.y = (g0 * (t0.y + t4.y) + g1 * (t1.y + t3.y) + g2 * t2.y) * invn;
        o.z = (g0 * (t0.z + t4.z) + g1 * (t1.z + t3.z) + g2 * t2.z) * invn;
        o.w = (g0 * (t0.w + t4.w) + g1 * (t1.w + t3.w) + g2 * t2.w) * invn;
        reinterpret_cast<float4*>(gout)[idx] = o;
    }
}

extern "C" void kernel_launch(void* const* d_in, const int* in_sizes, int n_in,
                              void* d_out, int out_size) {
    const float* x = (const float*)d_in[0];
    const float* sigma = (const float*)d_in[1];
    float* out = (float*)d_out;
    int planes = in_sizes[0] / (HH * WW);   // 16 * 256 = 4096
    gauss5_kernel<<<planes, TPB>>>(x, sigma, out);
}

// round 2
// speedup vs baseline: 1.0549x; 1.0549x over previous
#include <cuda_runtime.h>
#include <math.h>

// Depthwise 5x5 Gaussian blur, separable.
// Horizontal pass: in registers via warp shuffles (segment width 16 = one row).
// Vertical pass: smem temp buffer, 4-row register reuse per thread.
// x: [16, 256, 64, 64] f32, sigma: [1] f32. One block per 64x64 plane.

#define HH 64
#define WW 64
#define TPB 256

__global__ __launch_bounds__(TPB) void gauss5_kernel(const float* __restrict__ x,
                                                     const float* __restrict__ sigma_p,
                                                     float* __restrict__ out)
{
    __shared__ float stmp[(HH + 4) * WW];   // horizontal result; data rows 2..65, halo rows zero

    const int tid = threadIdx.x;
    const long plane = blockIdx.x;          // n*C + c
    const float4* gin = reinterpret_cast<const float4*>(x + plane * (long)(HH * WW));
    float4* gout = reinterpret_cast<float4*>(out + plane * (long)(HH * WW));

    // Gaussian taps (symmetric), g2 folded to 1; normalize at the end.
    const float sigma = sigma_p[0];
    const float inv2s2 = 1.0f / (2.0f * sigma * sigma);
    const float g0 = expf(-4.0f * inv2s2);   // |d| = 2
    const float g1 = expf(-1.0f * inv2s2);   // |d| = 1
    const float s1 = 2.0f * (g0 + g1) + 1.0f;
    const float invn = 1.0f / (s1 * s1);

    // zero temp row halos: rows {0,1,66,67} x 64 cols = 256 floats, one per thread
    {
        int r = tid >> 6;            // 0..3
        int c = tid & 63;
        int row = (r < 2) ? r : (r + 64);
        stmp[row * WW + c] = 0.0f;
    }

    const int qc = tid & 15;         // float4 column index within row (shuffle segment pos)

    // --- load + horizontal pass in registers ---
    #pragma unroll
    for (int i = 0; i < 4; i++) {
        int idx = tid + i * TPB;     // 0..1023 = float4 index in plane
        int r = idx >> 4;
        float4 b = gin[idx];
        // neighbors from adjacent lanes within the 16-lane row segment
        float pz = __shfl_up_sync(0xffffffffu, b.z, 1, 16);   // col c4-2
        float pw = __shfl_up_sync(0xffffffffu, b.w, 1, 16);   // col c4-1
        float nx = __shfl_down_sync(0xffffffffu, b.x, 1, 16); // col c4+4
        float ny = __shfl_down_sync(0xffffffffu, b.y, 1, 16); // col c4+5
        if (qc == 0)  { pz = 0.0f; pw = 0.0f; }               // left zero-pad
        if (qc == 15) { nx = 0.0f; ny = 0.0f; }               // right zero-pad
        float4 t;
        t.x = g0 * (pz + b.z)  + g1 * (pw + b.y) + b.x;
        t.y = g0 * (pw + b.w)  + g1 * (b.x + b.z) + b.y;
        t.z = g0 * (b.x + nx)  + g1 * (b.y + b.w) + b.z;
        t.w = g0 * (b.y + ny)  + g1 * (b.z + nx) + b.w;
        *reinterpret_cast<float4*>(&stmp[(r + 2) * WW + (qc << 2)]) = t;
    }
    __syncthreads();

    // --- vertical pass: each thread does a 4col x 4row tile ---
    // tid -> c4 = tid & 15 (float4 col), rb = tid >> 4 (row block of 4)
    const int rb = tid >> 4;
    const float* colp = &stmp[(rb << 2) * WW + (qc << 2)];  // padded rows rb*4 .. rb*4+7

    float4 t0 = *reinterpret_cast<const float4*>(colp);
    float4 t1 = *reinterpret_cast<const float4*>(colp + WW);
    float4 t2 = *reinterpret_cast<const float4*>(colp + 2 * WW);
    float4 t3 = *reinterpret_cast<const float4*>(colp + 3 * WW);
    float4 t4 = *reinterpret_cast<const float4*>(colp + 4 * WW);
    float4 t5 = *reinterpret_cast<const float4*>(colp + 5 * WW);
    float4 t6 = *reinterpret_cast<const float4*>(colp + 6 * WW);
    float4 t7 = *reinterpret_cast<const float4*>(colp + 7 * WW);

    const int obase = (rb << 2) * 16 + qc;   // float4 index of output row rb*4, col group qc

    float4 o;
    o.x = (g0 * (t0.x + t4.x) + g1 * (t1.x + t3.x) + t2.x) * invn;
    o.y = (g0 * (t0.y + t4.y) + g1 * (t1.y + t3.y) + t2.y) * invn;
    o.z = (g0 * (t0.z + t4.z) + g1 * (t1.z + t3.z) + t2.z) * invn;
    o.w = (g0 * (t0.w + t4.w) + g1 * (t1.w + t3.w) + t2.w) * invn;
    gout[obase] = o;

    o.x = (g0 * (t1.x + t5.x) + g1 * (t2.x + t4.x) + t3.x) * invn;
    o.y = (g0 * (t1.y + t5.y) + g1 * (t2.y + t4.y) + t3.y) * invn;
    o.z = (g0 * (t1.z + t5.z) + g1 * (t2.z + t4.z) + t3.z) * invn;
    o.w = (g0 * (t1.w + t5.w) + g1 * (t2.w + t4.w) + t3.w) * invn;
    gout[obase + 16] = o;

    o.x = (g0 * (t2.x + t6.x) + g1 * (t3.x + t5.x) + t4.x) * invn;
    o.y = (g0 * (t2.y + t6.y) + g1 * (t3.y + t5.y) + t4.y) * invn;
    o.z = (g0 * (t2.z + t6.z) + g1 * (t3.z + t5.z) + t4.z) * invn;
    o.w = (g0 * (t2.w + t6.w) + g1 * (t3.w + t5.w) + t4.w) * invn;
    gout[obase + 32] = o;

    o.x = (g0 * (t3.x + t7.x) + g1 * (t4.x + t6.x) + t5.x) * invn;
    o.y = (g0 * (t3.y + t7.y) + g1 * (t4.y + t6.y) + t5.y) * invn;
    o.z = (g0 * (t3.z + t7.z) + g1 * (t4.z + t6.z) + t5.z) * invn;
    o.w = (g0 * (t3.w + t7.w) + g1 * (t4.w + t6.w) + t5.w) * invn;
    gout[obase + 48] = o;
}

extern "C" void kernel_launch(void* const* d_in, const int* in_sizes, int n_in,
                              void* d_out, int out_size) {
    const float* x = (const float*)d_in[0];
    const float* sigma = (const float*)d_in[1];
    float* out = (float*)d_out;
    int planes = in_sizes[0] / (HH * WW);   // 16 * 256 = 4096
    gauss5_kernel<<<planes, TPB>>>(x, sigma, out);
}

// round 3
// speedup vs baseline: 1.3359x; 1.2664x over previous
#include <cuda_runtime.h>
#include <math.h>

// Depthwise 5x5 Gaussian blur, separable.
// Horizontal pass: registers + warp shuffles (16-lane segments = one image row).
// Vertical pass: 8-row register tile per thread; only boundary rows (+-2) cross
// threads via a compact shared buffer.
// x: [16, 256, 64, 64] f32, sigma: [1] f32. 2 planes per 256-thread block.

#define HH 64
#define WW 64
#define TPB 256

__global__ __launch_bounds__(TPB) void gauss5_kernel(const float* __restrict__ x,
                                                     const float* __restrict__ sigma_p,
                                                     float* __restrict__ out)
{
    // boundary buffer: per plane, 9 groups x 4 rows x 16 float4 (cols)
    // group b holds horiz-result rows 8b-2, 8b-1, 8b, 8b+1 (slots 0..3)
    __shared__ float4 sbuf[2 * 9 * 4 * 16];   // 18 KB

    const int tid = threadIdx.x;
    const int p   = tid >> 7;        // plane within block (0/1)
    const int wg  = tid & 127;
    const int rb  = wg >> 4;         // 8-row block index (0..7)
    const int qc  = wg & 15;         // float4 column group (0..15)

    const int plane = blockIdx.x * 2 + p;
    const float4* gin  = reinterpret_cast<const float4*>(x)   + plane * 1024;
    float4*       gout = reinterpret_cast<float4*>(out)       + plane * 1024;

    // Gaussian taps (symmetric), center tap folded to 1; normalize at the end.
    const float sigma = sigma_p[0];
    const float inv2s2 = 1.0f / (2.0f * sigma * sigma);
    const float g0 = expf(-4.0f * inv2s2);   // |d| = 2
    const float g1 = expf(-1.0f * inv2s2);   // |d| = 1
    const float s1 = 2.0f * (g0 + g1) + 1.0f;
    const float invn = 1.0f / (s1 * s1);

    // zero halo groups: plane edge rows (-2,-1) -> group 0 slots 0,1
    //                   rows (64,65)           -> group 8 slots 2,3
    if (tid < 128) {
        int ph   = tid >> 6;        // plane
        int rest = tid & 63;
        int hr   = rest >> 4;       // 0..3 -> slot
        int c4   = rest & 15;
        int g    = (hr < 2) ? 0 : 8;
        sbuf[((ph * 9 + g) * 4 + hr) * 16 + c4] = make_float4(0.f, 0.f, 0.f, 0.f);
    }

    const int base = (rb << 3) * 16 + qc;    // float4 index of (row rb*8, colgroup qc)

    // --- load 8 rows + horizontal pass in registers ---
    float4 t[8];
    #pragma unroll
    for (int j = 0; j < 8; j++) {
        float4 b = gin[base + j * 16];
        float pz = __shfl_up_sync(0xffffffffu, b.z, 1, 16);   // col-2
        float pw = __shfl_up_sync(0xffffffffu, b.w, 1, 16);   // col-1
        float nx = __shfl_down_sync(0xffffffffu, b.x, 1, 16); // col+4
        float ny = __shfl_down_sync(0xffffffffu, b.y, 1, 16); // col+5
        if (qc == 0)  { pz = 0.0f; pw = 0.0f; }
        if (qc == 15) { nx = 0.0f; ny = 0.0f; }
        t[j].x = g0 * (pz + b.z) + g1 * (pw + b.y) + b.x;
        t[j].y = g0 * (pw + b.w) + g1 * (b.x + b.z) + b.y;
        t[j].z = g0 * (b.x + nx) + g1 * (b.y + b.w) + b.z;
        t[j].w = g0 * (b.y + ny) + g1 * (b.z + nx) + b.w;
    }

    // --- share boundary rows through smem ---
    float4* sp = &sbuf[(p * 9) * 4 * 16];
    sp[(rb * 4 + 2) * 16 + qc]       = t[0];   // row 8rb   -> group rb,   slot 2
    sp[(rb * 4 + 3) * 16 + qc]       = t[1];   // row 8rb+1 -> group rb,   slot 3
    sp[((rb + 1) * 4 + 0) * 16 + qc] = t[6];   // row 8rb+6 -> group rb+1, slot 0
    sp[((rb + 1) * 4 + 1) * 16 + qc] = t[7];   // row 8rb+7 -> group rb+1, slot 1
    __syncthreads();

    float4 w0  = sp[(rb * 4 + 0) * 16 + qc];        // row 8rb-2
    float4 w1  = sp[(rb * 4 + 1) * 16 + qc];        // row 8rb-1
    float4 w10 = sp[((rb + 1) * 4 + 2) * 16 + qc];  // row 8rb+8
    float4 w11 = sp[((rb + 1) * 4 + 3) * 16 + qc];  // row 8rb+9

    // --- vertical pass on 12-row window [w0,w1,t0..t7,w10,w11] ---
    float4 w[12];
    w[0] = w0; w[1] = w1;
    #pragma unroll
    for (int j = 0; j < 8; j++) w[2 + j] = t[j];
    w[10] = w10; w[11] = w11;

    #pragma unroll
    for (int j = 0; j < 8; j++) {
        float4 o;
        o.x = (g0 * (w[j].x + w[j+4].x) + g1 * (w[j+1].x + w[j+3].x) + w[j+2].x) * invn;
        o.y = (g0 * (w[j].y + w[j+4].y) + g1 * (w[j+1].y + w[j+3].y) + w[j+2].y) * invn;
        o.z = (g0 * (w[j].z + w[j+4].z) + g1 * (w[j+1].z + w[j+3].z) + w[j+2].z) * invn;
        o.w = (g0 * (w[j].w + w[j+4].w) + g1 * (w[j+1].w + w[j+3].w) + w[j+2].w) * invn;
        gout[base + j * 16] = o;
    }
}

extern "C" void kernel_launch(void* const* d_in, const int* in_sizes, int n_in,
                              void* d_out, int out_size) {
    const float* x = (const float*)d_in[0];
    const float* sigma = (const float*)d_in[1];
    float* out = (float*)d_out;
    int planes = in_sizes[0] / (HH * WW);   // 4096
    gauss5_kernel<<<planes / 2, TPB>>>(x, sigma, out);
}

// round 4
// speedup vs baseline: 1.3463x; 1.0078x over previous
#include <cuda_runtime.h>
#include <math.h>

// Depthwise 5x5 Gaussian blur, separable.
// Horizontal pass: registers + full-warp shuffles (one warp = one image row).
// Vertical pass: 8-row x 2-col register tile/thread; boundary rows (+-2)
// exchanged via a compact shared buffer.
// x: [16, 256, 64, 64] f32, sigma: [1] f32. One 64x64 plane per 256-thread block.

#define HH 64
#define WW 64
#define TPB 256

__global__ __launch_bounds__(TPB) void gauss5_kernel(const float* __restrict__ x,
                                                     const float* __restrict__ sigma_p,
                                                     float* __restrict__ out)
{
    // boundary buffer: 9 groups x 4 row-slots x 32 float2 (cols).
    // group b holds horiz-result rows 8b-2, 8b-1, 8b, 8b+1 (slots 0..3)
    __shared__ float2 sbuf[9 * 4 * 32];   // 9 KB

    const int tid  = threadIdx.x;
    const int rb   = tid >> 5;        // 8-row block index (0..7)
    const int lane = tid & 31;        // float2 column group (0..31)

    const int plane = blockIdx.x;
    const float2* gin  = reinterpret_cast<const float2*>(x)   + plane * 2048;
    float2*       gout = reinterpret_cast<float2*>(out)       + plane * 2048;

    // Gaussian taps (symmetric), center tap folded to 1; normalize at the end.
    const float sigma = sigma_p[0];
    const float inv2s2 = 1.0f / (2.0f * sigma * sigma);
    const float g0 = expf(-4.0f * inv2s2);   // |d| = 2
    const float g1 = expf(-1.0f * inv2s2);   // |d| = 1
    const float s1 = 2.0f * (g0 + g1) + 1.0f;
    const float invn = 1.0f / (s1 * s1);

    // zero halo rows: plane rows (-2,-1) -> group 0 slots 0,1
    //                 plane rows (64,65) -> group 8 slots 2,3
    if (tid < 128) {
        int hr = tid >> 5;            // 0..3
        int c  = tid & 31;
        int g  = (hr < 2) ? 0 : 8;
        sbuf[(g * 4 + hr) * 32 + c] = make_float2(0.f, 0.f);
    }

    const int base = (rb << 3) * 32 + lane;   // float2 index of (row rb*8, col pair lane)

    // --- load 8 rows + horizontal pass in registers ---
    float2 t[8];
    #pragma unroll
    for (int j = 0; j < 8; j++) {
        float2 b = gin[base + j * 32];
        float px = __shfl_up_sync(0xffffffffu, b.x, 1);    // col 2c-2
        float py = __shfl_up_sync(0xffffffffu, b.y, 1);    // col 2c-1
        float nx = __shfl_down_sync(0xffffffffu, b.x, 1);  // col 2c+2
        float ny = __shfl_down_sync(0xffffffffu, b.y, 1);  // col 2c+3
        if (lane == 0)  { px = 0.0f; py = 0.0f; }          // left zero-pad
        if (lane == 31) { nx = 0.0f; ny = 0.0f; }          // right zero-pad
        t[j].x = g0 * (px + nx) + g1 * (py + b.y) + b.x;
        t[j].y = g0 * (py + ny) + g1 * (b.x + nx) + b.y;
    }

    // --- share boundary rows through smem ---
    sbuf[(rb * 4 + 2) * 32 + lane]       = t[0];   // row 8rb   -> group rb,   slot 2
    sbuf[(rb * 4 + 3) * 32 + lane]       = t[1];   // row 8rb+1 -> group rb,   slot 3
    sbuf[((rb + 1) * 4 + 0) * 32 + lane] = t[6];   // row 8rb+6 -> group rb+1, slot 0
    sbuf[((rb + 1) * 4 + 1) * 32 + lane] = t[7];   // row 8rb+7 -> group rb+1, slot 1
    __syncthreads();

    float2 wm2 = sbuf[(rb * 4 + 0) * 32 + lane];        // row 8rb-2
    float2 wm1 = sbuf[(rb * 4 + 1) * 32 + lane];        // row 8rb-1
    float2 wp8 = sbuf[((rb + 1) * 4 + 2) * 32 + lane];  // row 8rb+8
    float2 wp9 = sbuf[((rb + 1) * 4 + 3) * 32 + lane];  // row 8rb+9

    // --- vertical pass on 12-row window ---
    float2 w[12];
    w[0] = wm2; w[1] = wm1;
    #pragma unroll
    for (int j = 0; j < 8; j++) w[2 + j] = t[j];
    w[10] = wp8; w[11] = wp9;

    #pragma unroll
    for (int j = 0; j < 8; j++) {
        float2 o;
        o.x = (g0 * (w[j].x + w[j+4].x) + g1 * (w[j+1].x + w[j+3].x) + w[j+2].x) * invn;
        o.y = (g0 * (w[j].y + w[j+4].y) + g1 * (w[j+1].y + w[j+3].y) + w[j+2].y) * invn;
        gout[base + j * 32] = o;
    }
}

extern "C" void kernel_launch(void* const* d_in, const int* in_sizes, int n_in,
                              void* d_out, int out_size) {
    const float* x = (const float*)d_in[0];
    const float* sigma = (const float*)d_in[1];
    float* out = (float*)d_out;
    int planes = in_sizes[0] / (HH * WW);   // 4096
    gauss5_kernel<<<planes, TPB>>>(x, sigma, out);
}